// round 1
// baseline (speedup 1.0000x reference)
#include <cuda_runtime.h>
#include <cuda_bf16.h>
#include <cstdint>

// Problem constants
#define NB   2
#define C_   256
#define CI_  128
#define NN   65536            // D*H*W = 16*64*64
#define CK   2048             // k-chunk per syrk block
#define KT   32               // k-tile in smem

// ---------------- scratch (static device globals; no allocation) ----------------
__device__ float d_S[NB][C_][C_];      // X X^T per batch
__device__ float d_s[NB][C_];          // row sums
__device__ float d_u[NB][CI_];         // phi_w @ s
__device__ float d_v[NB][CI_];         // g_w @ s
__device__ float d_T1[NB][CI_][C_];    // phi_w @ S
__device__ float d_kv[NB][CI_][CI_];
__device__ float d_M[NB][C_][CI_];     // W_w kv^T / N
__device__ float d_A[NB][C_][C_];      // M @ theta_w
__device__ float d_b2[NB][C_];         // M @ theta_b + W_b

// ---------------- zero the accumulated buffers (S is atomicAdd target) ----------
__global__ void zero_kernel() {
    int idx = blockIdx.x * blockDim.x + threadIdx.x;
    float* p = &d_S[0][0][0];
    if (idx < NB * C_ * C_) p[idx] = 0.0f;
}

// ---------------- row sums: s[b][c] = sum_n x[b][c][n] ---------------------------
__global__ void rowsum_kernel(const float* __restrict__ x) {
    int b = blockIdx.y, c = blockIdx.x;
    const float4* p = (const float4*)(x + (size_t)(b * C_ + c) * NN);
    float acc = 0.0f;
    for (int i = threadIdx.x; i < NN / 4; i += 256) {
        float4 v = p[i];
        acc += v.x + v.y + v.z + v.w;
    }
    __shared__ float red[256];
    red[threadIdx.x] = acc;
    __syncthreads();
    for (int s = 128; s > 0; s >>= 1) {
        if (threadIdx.x < s) red[threadIdx.x] += red[threadIdx.x + s];
        __syncthreads();
    }
    if (threadIdx.x == 0) d_s[b][c] = red[0];
}

// ---------------- syrk: S[b] += X_b[128-quad rows] * X_b[128-quad rows]^T --------
// grid (NN/CK, 4, NB); block 256 (16x16); each thread an 8x8 micro-tile.
__global__ __launch_bounds__(256, 2) void syrk_kernel(const float* __restrict__ x) {
    int b  = blockIdx.z;
    int qm = blockIdx.y >> 1, qn = blockIdx.y & 1;
    int k0 = blockIdx.x * CK;
    __shared__ float As[KT][132];
    __shared__ float Bs[KT][132];
    int tid = threadIdx.x;
    int ty = tid >> 4, tx = tid & 15;
    float acc[8][8] = {};
    const float* xb = x + (size_t)b * C_ * NN;

    for (int kk = 0; kk < CK; kk += KT) {
#pragma unroll
        for (int l = 0; l < 4; l++) {
            int lin = tid + l * 256;           // float4 index over [128 rows][8 f4]
            int row = lin >> 3, c4 = lin & 7;
            float4 va = *(const float4*)(xb + (size_t)(qm * 128 + row) * NN + (k0 + kk + c4 * 4));
            As[c4 * 4 + 0][row] = va.x; As[c4 * 4 + 1][row] = va.y;
            As[c4 * 4 + 2][row] = va.z; As[c4 * 4 + 3][row] = va.w;
            float4 vb = *(const float4*)(xb + (size_t)(qn * 128 + row) * NN + (k0 + kk + c4 * 4));
            Bs[c4 * 4 + 0][row] = vb.x; Bs[c4 * 4 + 1][row] = vb.y;
            Bs[c4 * 4 + 2][row] = vb.z; Bs[c4 * 4 + 3][row] = vb.w;
        }
        __syncthreads();
#pragma unroll
        for (int k = 0; k < KT; k++) {
            float a[8], bb[8];
            *(float4*)(a)      = *(const float4*)&As[k][ty * 8];
            *(float4*)(a + 4)  = *(const float4*)&As[k][ty * 8 + 4];
            *(float4*)(bb)     = *(const float4*)&Bs[k][tx * 8];
            *(float4*)(bb + 4) = *(const float4*)&Bs[k][tx * 8 + 4];
#pragma unroll
            for (int i = 0; i < 8; i++)
#pragma unroll
                for (int j = 0; j < 8; j++) acc[i][j] += a[i] * bb[j];
        }
        __syncthreads();
    }
#pragma unroll
    for (int i = 0; i < 8; i++)
#pragma unroll
        for (int j = 0; j < 8; j++)
            atomicAdd(&d_S[b][qm * 128 + ty * 8 + i][qn * 128 + tx * 8 + j], acc[i][j]);
}

// ---------------- small chain ----------------------------------------------------
__global__ void uv_kernel(const float* __restrict__ phi_w, const float* __restrict__ g_w) {
    int b = blockIdx.y, i = threadIdx.x;
    float su = 0.0f, sv = 0.0f;
    for (int c = 0; c < C_; c++) {
        float sc = d_s[b][c];
        su += phi_w[i * C_ + c] * sc;
        sv += g_w[i * C_ + c] * sc;
    }
    d_u[b][i] = su;
    d_v[b][i] = sv;
}

// T1[b][i][c2] = sum_c phi_w[i][c] * S[b][c][c2];  block = one row i, threads = c2
__global__ void t1_kernel(const float* __restrict__ phi_w) {
    int b = blockIdx.y, i = blockIdx.x, c2 = threadIdx.x;
    float acc = 0.0f;
    for (int c = 0; c < C_; c++) acc += phi_w[i * C_ + c] * d_S[b][c][c2];
    d_T1[b][i][c2] = acc;
}

__global__ void kv_kernel(const float* __restrict__ g_w, const float* __restrict__ g_b,
                          const float* __restrict__ phi_b) {
    int b = blockIdx.y, i = blockIdx.x, j = threadIdx.x;
    float acc = 0.0f;
    for (int d = 0; d < C_; d++) acc += d_T1[b][i][d] * g_w[j * C_ + d];
    acc += d_u[b][i] * g_b[j] + phi_b[i] * d_v[b][j] + (float)NN * phi_b[i] * g_b[j];
    d_kv[b][i][j] = acc;
}

__global__ void m_kernel(const float* __restrict__ W_w) {
    int b = blockIdx.y, c = blockIdx.x, i = threadIdx.x;
    float acc = 0.0f;
    for (int j = 0; j < CI_; j++) acc += W_w[c * CI_ + j] * d_kv[b][i][j];
    d_M[b][c][i] = acc * (1.0f / (float)NN);
}

__global__ void a_kernel(const float* __restrict__ theta_w, const float* __restrict__ theta_b,
                         const float* __restrict__ W_b) {
    int b = blockIdx.y, c = blockIdx.x, dd = threadIdx.x;
    float acc = 0.0f;
    for (int i = 0; i < CI_; i++) acc += d_M[b][c][i] * theta_w[i * C_ + dd];
    d_A[b][c][dd] = acc;
    if (dd == 0) {
        float bb = W_b[c];
        for (int i = 0; i < CI_; i++) bb += d_M[b][c][i] * theta_b[i];
        d_b2[b][c] = bb;
    }
}

// ---------------- pass 2: out = x + A x + b2 -------------------------------------
// grid (NN/128, 2, NB); block 256 (16x16); 128x128 tile, K=256.
__global__ __launch_bounds__(256, 2) void pass2_kernel(const float* __restrict__ x,
                                                       float* __restrict__ out) {
    int b = blockIdx.z;
    int m0 = blockIdx.y * 128;
    int n0 = blockIdx.x * 128;
    __shared__ float As[KT][132];
    __shared__ float Xs[KT][132];
    int tid = threadIdx.x;
    int ty = tid >> 4, tx = tid & 15;
    float acc[8][8] = {};
    const float* xb = x + (size_t)b * C_ * NN;
    const float* Ab = &d_A[b][0][0];

    for (int k0 = 0; k0 < C_; k0 += KT) {
#pragma unroll
        for (int l = 0; l < 4; l++) {
            int lin = tid + l * 256;
            // A tile: [128 rows][8 f4] -> transposed into As[k][m]
            int row = lin >> 3, c4 = lin & 7;
            float4 va = *(const float4*)(Ab + (size_t)(m0 + row) * C_ + (k0 + c4 * 4));
            As[c4 * 4 + 0][row] = va.x; As[c4 * 4 + 1][row] = va.y;
            As[c4 * 4 + 2][row] = va.z; As[c4 * 4 + 3][row] = va.w;
            // X tile: [32 k-rows][32 f4], natural layout Xs[k][n]
            int xrow = lin >> 5, xc4 = lin & 31;
            float4 vx = *(const float4*)(xb + (size_t)(k0 + xrow) * NN + (n0 + xc4 * 4));
            *(float4*)&Xs[xrow][xc4 * 4] = vx;
        }
        __syncthreads();
#pragma unroll
        for (int k = 0; k < KT; k++) {
            float a[8], xv[8];
            *(float4*)(a)      = *(const float4*)&As[k][ty * 8];
            *(float4*)(a + 4)  = *(const float4*)&As[k][ty * 8 + 4];
            *(float4*)(xv)     = *(const float4*)&Xs[k][tx * 8];
            *(float4*)(xv + 4) = *(const float4*)&Xs[k][tx * 8 + 4];
#pragma unroll
            for (int i = 0; i < 8; i++)
#pragma unroll
                for (int j = 0; j < 8; j++) acc[i][j] += a[i] * xv[j];
        }
        __syncthreads();
    }

    // epilogue: out = acc + x + b2  (residual in fp32)
#pragma unroll
    for (int i = 0; i < 8; i++) {
        int c = m0 + ty * 8 + i;
        float bias = d_b2[b][c];
        size_t off = (size_t)(b * C_ + c) * NN + n0 + tx * 8;
        float4 x0 = *(const float4*)(x + off);
        float4 x1 = *(const float4*)(x + off + 4);
        float4 o0, o1;
        o0.x = acc[i][0] + x0.x + bias; o0.y = acc[i][1] + x0.y + bias;
        o0.z = acc[i][2] + x0.z + bias; o0.w = acc[i][3] + x0.w + bias;
        o1.x = acc[i][4] + x1.x + bias; o1.y = acc[i][5] + x1.y + bias;
        o1.z = acc[i][6] + x1.z + bias; o1.w = acc[i][7] + x1.w + bias;
        *(float4*)(out + off)     = o0;
        *(float4*)(out + off + 4) = o1;
    }
}

// ---------------- launch ----------------------------------------------------------
extern "C" void kernel_launch(void* const* d_in, const int* in_sizes, int n_in,
                              void* d_out, int out_size) {
    const float* x       = (const float*)d_in[0];
    const float* g_w     = (const float*)d_in[1];
    const float* g_b     = (const float*)d_in[2];
    const float* theta_w = (const float*)d_in[3];
    const float* theta_b = (const float*)d_in[4];
    const float* phi_w   = (const float*)d_in[5];
    const float* phi_b   = (const float*)d_in[6];
    const float* W_w     = (const float*)d_in[7];
    const float* W_b     = (const float*)d_in[8];
    float* out = (float*)d_out;

    zero_kernel<<<(NB * C_ * C_ + 255) / 256, 256>>>();
    rowsum_kernel<<<dim3(C_, NB), 256>>>(x);
    syrk_kernel<<<dim3(NN / CK, 4, NB), 256>>>(x);
    uv_kernel<<<dim3(1, NB), CI_>>>(phi_w, g_w);
    t1_kernel<<<dim3(CI_, NB), C_>>>(phi_w);
    kv_kernel<<<dim3(CI_, NB), CI_>>>(g_w, g_b, phi_b);
    m_kernel<<<dim3(C_, NB), CI_>>>(W_w);
    a_kernel<<<dim3(C_, NB), C_>>>(theta_w, theta_b, W_b);
    pass2_kernel<<<dim3(NN / 128, 2, NB), 256>>>(x, out);
}